// round 2
// baseline (speedup 1.0000x reference)
#include <cuda_runtime.h>
#include <cstdint>

#define BATCH 16384
#define EDIM  256
#define HDIM  1024
#define ADIM  256
#define NLAYER 8

// Scratch (allocation-free rule: __device__ globals)
__device__ float g_x[(size_t)BATCH * HDIM];   // activations
__device__ float g_z[(size_t)BATCH * HDIM];   // pre-LN / hidden
__device__ float g_e[(size_t)BATCH * EDIM];   // final embedding-space output

__device__ __forceinline__ float f2tf32(float x) {
    float r;
    asm("cvt.rna.tf32.f32 %0, %1;" : "=f"(r) : "f"(x));
    return r;
}

// ---------------------------------------------------------------------------
// tf32 tensor-core GEMM: C[M,N] = act( A[M,K] @ W[K,N] + bias[N] )
// CTA tile 128x128x32, 256 threads (8 warps), warp tile 64x32 (2x4 warp grid)
// ---------------------------------------------------------------------------
template <bool RELU>
__global__ __launch_bounds__(256, 2)
void gemm_bias_kernel(const float* __restrict__ A, const float* __restrict__ W,
                      const float* __restrict__ bias, float* __restrict__ C,
                      int M, int N, int K)
{
    __shared__ __align__(16) float As[128][36];   // pad -> stride%32==4, conflict-free
    __shared__ __align__(16) float Bs[32][136];   // pad -> stride%32==8, conflict-free

    const int tid  = threadIdx.x;
    const int warp = tid >> 5;
    const int lane = tid & 31;
    const int wm = (warp & 1) * 64;   // warp row offset inside CTA tile
    const int wn = (warp >> 1) * 32;  // warp col offset
    const int g  = lane >> 2;         // groupID
    const int tg = lane & 3;          // threadID-in-group

    const int bm = blockIdx.y * 128;
    const int bn = blockIdx.x * 128;

    float acc[4][4][4];
    #pragma unroll
    for (int i = 0; i < 4; i++)
        #pragma unroll
        for (int j = 0; j < 4; j++)
            #pragma unroll
            for (int r = 0; r < 4; r++) acc[i][j][r] = 0.f;

    for (int k0 = 0; k0 < K; k0 += 32) {
        // --- load A tile 128x32 (coalesced float4), convert to tf32 ---
        #pragma unroll
        for (int i = 0; i < 4; i++) {
            int f   = tid + i * 256;          // 0..1023
            int row = f >> 3;                 // 0..127
            int c4  = f & 7;                  // 0..7
            float4 v = *(const float4*)(A + (size_t)(bm + row) * K + k0 + c4 * 4);
            v.x = f2tf32(v.x); v.y = f2tf32(v.y); v.z = f2tf32(v.z); v.w = f2tf32(v.w);
            *(float4*)&As[row][c4 * 4] = v;
        }
        // --- load B tile 32x128 ---
        #pragma unroll
        for (int i = 0; i < 4; i++) {
            int f   = tid + i * 256;
            int row = f >> 5;                 // 0..31
            int c4  = f & 31;                 // 0..31
            float4 v = *(const float4*)(W + (size_t)(k0 + row) * N + bn + c4 * 4);
            v.x = f2tf32(v.x); v.y = f2tf32(v.y); v.z = f2tf32(v.z); v.w = f2tf32(v.w);
            *(float4*)&Bs[row][c4 * 4] = v;
        }
        __syncthreads();

        #pragma unroll
        for (int kk = 0; kk < 32; kk += 8) {
            uint32_t a[4][4], b[4][2];
            #pragma unroll
            for (int mi = 0; mi < 4; mi++) {
                int r = wm + mi * 16 + g;
                a[mi][0] = __float_as_uint(As[r    ][kk + tg    ]);
                a[mi][1] = __float_as_uint(As[r + 8][kk + tg    ]);
                a[mi][2] = __float_as_uint(As[r    ][kk + tg + 4]);
                a[mi][3] = __float_as_uint(As[r + 8][kk + tg + 4]);
            }
            #pragma unroll
            for (int ni = 0; ni < 4; ni++) {
                int c = wn + ni * 8 + g;
                b[ni][0] = __float_as_uint(Bs[kk + tg    ][c]);
                b[ni][1] = __float_as_uint(Bs[kk + tg + 4][c]);
            }
            #pragma unroll
            for (int mi = 0; mi < 4; mi++)
                #pragma unroll
                for (int ni = 0; ni < 4; ni++)
                    asm volatile(
                        "mma.sync.aligned.m16n8k8.row.col.f32.tf32.tf32.f32 "
                        "{%0,%1,%2,%3},{%4,%5,%6,%7},{%8,%9},{%0,%1,%2,%3};"
                        : "+f"(acc[mi][ni][0]), "+f"(acc[mi][ni][1]),
                          "+f"(acc[mi][ni][2]), "+f"(acc[mi][ni][3])
                        : "r"(a[mi][0]), "r"(a[mi][1]), "r"(a[mi][2]), "r"(a[mi][3]),
                          "r"(b[ni][0]), "r"(b[ni][1]));
        }
        __syncthreads();
    }

    // --- epilogue: bias (+ReLU), fp32 store ---
    #pragma unroll
    for (int mi = 0; mi < 4; mi++) {
        int r0 = bm + wm + mi * 16 + g;
        #pragma unroll
        for (int ni = 0; ni < 4; ni++) {
            int c0 = bn + wn + ni * 8 + tg * 2;
            float bv0 = bias[c0], bv1 = bias[c0 + 1];
            float v0 = acc[mi][ni][0] + bv0;
            float v1 = acc[mi][ni][1] + bv1;
            float v2 = acc[mi][ni][2] + bv0;
            float v3 = acc[mi][ni][3] + bv1;
            if (RELU) {
                v0 = fmaxf(v0, 0.f); v1 = fmaxf(v1, 0.f);
                v2 = fmaxf(v2, 0.f); v3 = fmaxf(v3, 0.f);
            }
            *(float2*)(C + (size_t)r0 * N + c0)       = make_float2(v0, v1);
            *(float2*)(C + (size_t)(r0 + 8) * N + c0) = make_float2(v2, v3);
        }
    }
}

// ---------------------------------------------------------------------------
// LayerNorm (+optional residual):  x = [x +] LN(z) * gamma + beta, H=1024
// one CTA (256 threads) per row; float4 per thread
// ---------------------------------------------------------------------------
template <bool RES>
__global__ __launch_bounds__(256)
void ln_kernel(const float* __restrict__ z, float* __restrict__ x,
               const float* __restrict__ gamma, const float* __restrict__ beta)
{
    const int row = blockIdx.x;
    const int t   = threadIdx.x;

    float4 v = ((const float4*)(z + (size_t)row * HDIM))[t];
    float s  = v.x + v.y + v.z + v.w;
    float ss = v.x * v.x + v.y * v.y + v.z * v.z + v.w * v.w;

    #pragma unroll
    for (int o = 16; o; o >>= 1) {
        s  += __shfl_xor_sync(0xffffffffu, s, o);
        ss += __shfl_xor_sync(0xffffffffu, ss, o);
    }
    __shared__ float sbuf[16];
    const int w = t >> 5, l = t & 31;
    if (l == 0) { sbuf[w] = s; sbuf[8 + w] = ss; }
    __syncthreads();
    float tot = 0.f, tot2 = 0.f;
    #pragma unroll
    for (int i = 0; i < 8; i++) { tot += sbuf[i]; tot2 += sbuf[8 + i]; }

    const float inv = 1.f / (float)HDIM;
    float mu   = tot * inv;
    float var  = tot2 * inv - mu * mu;
    float rstd = rsqrtf(var + 1e-5f);

    float4 gm = ((const float4*)gamma)[t];
    float4 bt = ((const float4*)beta)[t];
    float4 o;
    o.x = (v.x - mu) * rstd * gm.x + bt.x;
    o.y = (v.y - mu) * rstd * gm.y + bt.y;
    o.z = (v.z - mu) * rstd * gm.z + bt.z;
    o.w = (v.w - mu) * rstd * gm.w + bt.w;
    if (RES) {
        float4 xv = ((const float4*)(x + (size_t)row * HDIM))[t];
        o.x += xv.x; o.y += xv.y; o.z += xv.z; o.w += xv.w;
    }
    ((float4*)(x + (size_t)row * HDIM))[t] = o;
}

// ---------------------------------------------------------------------------
// logits[b,a] = dot(xe[b,:], emb[b,a,:]); masked -> -inf
// one CTA per batch row b; warp-per-action, fully-coalesced float4 streams
// ---------------------------------------------------------------------------
__global__ __launch_bounds__(256)
void logits_kernel(const float* __restrict__ xe, const float* __restrict__ emb,
                   const int* __restrict__ idx, float* __restrict__ out)
{
    const int b = blockIdx.x;
    __shared__ float4 xs[EDIM / 4];
    const int t = threadIdx.x;
    if (t < EDIM / 4) xs[t] = ((const float4*)(xe + (size_t)b * EDIM))[t];
    __syncthreads();

    const int warp = t >> 5, lane = t & 31;
    for (int a = warp; a < ADIM; a += 8) {
        const float4* row = (const float4*)(emb + ((size_t)b * ADIM + a) * EDIM);
        float acc = 0.f;
        #pragma unroll
        for (int i = 0; i < 2; i++) {
            float4 v  = row[lane + 32 * i];
            float4 xv = xs[lane + 32 * i];
            acc += v.x * xv.x + v.y * xv.y + v.z * xv.z + v.w * xv.w;
        }
        #pragma unroll
        for (int o = 16; o; o >>= 1) acc += __shfl_xor_sync(0xffffffffu, acc, o);
        if (lane == 0) {
            int4 ii = ((const int4*)idx)[(size_t)b * ADIM + a];
            bool mask = (ii.x + ii.y + ii.z + ii.w) == 0;
            out[(size_t)b * ADIM + a] = mask ? __int_as_float(0xff800000) : acc;
        }
    }
}

// ---------------------------------------------------------------------------
extern "C" void kernel_launch(void* const* d_in, const int* in_sizes, int n_in,
                              void* d_out, int out_size)
{
    (void)in_sizes; (void)n_in; (void)out_size;
    const float* obs   = (const float*)d_in[0];
    const float* emb   = (const float*)d_in[1];
    const int*   idx   = (const int*)d_in[2];
    const float* w0    = (const float*)d_in[3];
    const float* b0    = (const float*)d_in[4];
    const float* g0    = (const float*)d_in[5];
    const float* be0   = (const float*)d_in[6];
    const float* Wb    = (const float*)d_in[7];
    const float* bb    = (const float*)d_in[8];
    const float* gb    = (const float*)d_in[9];
    const float* betab = (const float*)d_in[10];
    const float* w1    = (const float*)d_in[11];
    const float* b1    = (const float*)d_in[12];
    const float* w2    = (const float*)d_in[13];
    const float* b2    = (const float*)d_in[14];
    float* out = (float*)d_out;

    float *x, *z, *e;
    cudaGetSymbolAddress((void**)&x, g_x);
    cudaGetSymbolAddress((void**)&z, g_z);
    cudaGetSymbolAddress((void**)&e, g_e);

    const dim3 blk(256);
    const dim3 gridH(HDIM / 128, BATCH / 128);   // (8, 128)
    const dim3 gridE(EDIM / 128, BATCH / 128);   // (2, 128)

    // obs_transform: z = relu(obs @ w0 + b0); x = LN(z)
    gemm_bias_kernel<true><<<gridH, blk>>>(obs, w0, b0, z, BATCH, HDIM, EDIM);
    ln_kernel<false><<<BATCH, blk>>>(z, x, g0, be0);

    // 8 residual blocks: x += LN(relu(x @ Wb[i] + bb[i]))
    for (int i = 0; i < NLAYER; i++) {
        gemm_bias_kernel<true><<<gridH, blk>>>(x, Wb + (size_t)i * HDIM * HDIM,
                                               bb + (size_t)i * HDIM, z,
                                               BATCH, HDIM, HDIM);
        ln_kernel<true><<<BATCH, blk>>>(z, x, gb + (size_t)i * HDIM,
                                        betab + (size_t)i * HDIM);
    }

    // out_transform: e = relu(x @ w1 + b1) @ w2 + b2
    gemm_bias_kernel<true><<<gridH, blk>>>(x, w1, b1, z, BATCH, HDIM, HDIM);
    gemm_bias_kernel<false><<<gridE, blk>>>(z, w2, b2, e, BATCH, EDIM, HDIM);

    // logits + mask
    logits_kernel<<<BATCH, blk>>>(e, emb, idx, out);
}

// round 5
// speedup vs baseline: 1.3305x; 1.3305x over previous
#include <cuda_runtime.h>
#include <cstdint>

#define BATCH 16384
#define EDIM  256
#define HDIM  1024
#define ADIM  256
#define NLAYER 8
#define STAGES 4

// ---------------- scratch (__device__ globals; no allocs allowed) ----------
__device__ float g_x [(size_t)BATCH * HDIM];   // fp32 residual stream
__device__ float g_xr[(size_t)BATCH * HDIM];   // tf32-rounded GEMM input
__device__ float g_z [(size_t)BATCH * HDIM];
__device__ float g_e [(size_t)BATCH * EDIM];
__device__ float g_a0[(size_t)BATCH * EDIM];
// tf32-rounded weights (original [K,N] layout): wt0 | wtb[8] | wt1 | wt2
#define WT0_OFF 0
#define WTB_OFF (WT0_OFF + (size_t)EDIM * HDIM)
#define WT1_OFF (WTB_OFF + (size_t)NLAYER * HDIM * HDIM)
#define WT2_OFF (WT1_OFF + (size_t)HDIM * HDIM)
__device__ float g_wt[WT2_OFF + (size_t)HDIM * EDIM];

__device__ __forceinline__ float f2tf32(float x) {
    float r; asm("cvt.rna.tf32.f32 %0, %1;" : "=f"(r) : "f"(x)); return r;
}
__device__ __forceinline__ uint32_t smem_u32(const void* p) {
    uint32_t a;
    asm("{ .reg .u64 t; cvta.to.shared.u64 t, %1; cvt.u32.u64 %0, t; }"
        : "=r"(a) : "l"(p));
    return a;
}
__device__ __forceinline__ void cp16(uint32_t dst, const void* src) {
    asm volatile("cp.async.cg.shared.global [%0], [%1], 16;" :: "r"(dst), "l"(src));
}
#define CP_COMMIT() asm volatile("cp.async.commit_group;" ::: "memory")
#define CP_WAIT2()  asm volatile("cp.async.wait_group 2;" ::: "memory")

// ---------------------------------------------------------------------------
// Pipelined tf32 GEMM: C[M,N] = act( A[M,K] @ W[K,N] + bias[N] )
// CTA tile 128x128x32, 256 threads (8 warps), warp tile 64x32
// 4-stage cp.async ring; inputs must already be tf32-rounded bit patterns.
// ---------------------------------------------------------------------------
#define A_TILE (128 * 36)
#define B_TILE (32 * 136)
#define GEMM_SMEM_FLOATS (STAGES * (A_TILE + B_TILE))
#define GEMM_SMEM_BYTES  (GEMM_SMEM_FLOATS * 4)

__global__ __launch_bounds__(256, 1)
void gemm_pipe(const float* __restrict__ A, const float* __restrict__ W,
               const float* __restrict__ bias, float* __restrict__ C,
               int N, int K, int relu, int rnd)
{
    extern __shared__ float sm[];
    float* As = sm;                          // [STAGES][128][36]
    float* Bs = sm + STAGES * A_TILE;        // [STAGES][32][136]
    const uint32_t sA = smem_u32(As);
    const uint32_t sB = smem_u32(Bs);

    const int tid  = threadIdx.x;
    const int warp = tid >> 5;
    const int lane = tid & 31;
    const int wm = (warp & 1) * 64;
    const int wn = (warp >> 1) * 32;
    const int g  = lane >> 2;
    const int tg = lane & 3;

    const int bm = blockIdx.y * 128;
    const int bn = blockIdx.x * 128;
    const int ns = K >> 5;

    float acc[4][4][4];
    #pragma unroll
    for (int i = 0; i < 4; i++)
        #pragma unroll
        for (int j = 0; j < 4; j++)
            #pragma unroll
            for (int r = 0; r < 4; r++) acc[i][j][r] = 0.f;

    auto load_stage = [&](int s, int buf) {
        const int k0 = s << 5;
        #pragma unroll
        for (int i = 0; i < 4; i++) {
            int f = tid + i * 256;
            int row = f >> 3, c4 = f & 7;
            cp16(sA + (buf * A_TILE + row * 36 + c4 * 4) * 4,
                 A + (size_t)(bm + row) * K + k0 + c4 * 4);
        }
        #pragma unroll
        for (int i = 0; i < 4; i++) {
            int f = tid + i * 256;
            int row = f >> 5, c4 = f & 31;
            cp16(sB + (buf * B_TILE + row * 136 + c4 * 4) * 4,
                 W + (size_t)(k0 + row) * N + bn + c4 * 4);
        }
    };

    uint32_t af[2][4][4], bf[2][4][2];

    auto ldfrag = [&](int buf, int kk, uint32_t (&a)[4][4], uint32_t (&b)[4][2]) {
        const float* ab = As + buf * A_TILE;
        const float* bb = Bs + buf * B_TILE;
        #pragma unroll
        for (int mi = 0; mi < 4; mi++) {
            int r = wm + mi * 16 + g;
            a[mi][0] = __float_as_uint(ab[(r    ) * 36 + kk + tg    ]);
            a[mi][1] = __float_as_uint(ab[(r + 8) * 36 + kk + tg    ]);
            a[mi][2] = __float_as_uint(ab[(r    ) * 36 + kk + tg + 4]);
            a[mi][3] = __float_as_uint(ab[(r + 8) * 36 + kk + tg + 4]);
        }
        #pragma unroll
        for (int ni = 0; ni < 4; ni++) {
            int c = wn + ni * 8 + g;
            b[ni][0] = __float_as_uint(bb[(kk + tg    ) * 136 + c]);
            b[ni][1] = __float_as_uint(bb[(kk + tg + 4) * 136 + c]);
        }
    };

    #pragma unroll
    for (int s = 0; s < STAGES - 1; s++) {
        load_stage(s, s);
        CP_COMMIT();
    }
    CP_WAIT2();
    __syncthreads();
    ldfrag(0, 0, af[0], bf[0]);

    for (int s = 0; s < ns; s++) {
        const int buf = s & (STAGES - 1);
        if (s + STAGES - 1 < ns)
            load_stage(s + STAGES - 1, (s + STAGES - 1) & (STAGES - 1));
        CP_COMMIT();

        #pragma unroll
        for (int kki = 0; kki < 4; kki++) {
            const int cur = kki & 1, nxt = cur ^ 1;
            if (kki == 3) {
                CP_WAIT2();
                __syncthreads();
            }
            if (kki < 3) {
                ldfrag(buf, (kki + 1) * 8, af[nxt], bf[nxt]);
            } else if (s + 1 < ns) {
                ldfrag((s + 1) & (STAGES - 1), 0, af[nxt], bf[nxt]);
            }
            #pragma unroll
            for (int mi = 0; mi < 4; mi++)
                #pragma unroll
                for (int ni = 0; ni < 4; ni++)
                    asm volatile(
                        "mma.sync.aligned.m16n8k8.row.col.f32.tf32.tf32.f32 "
                        "{%0,%1,%2,%3},{%4,%5,%6,%7},{%8,%9},{%0,%1,%2,%3};"
                        : "+f"(acc[mi][ni][0]), "+f"(acc[mi][ni][1]),
                          "+f"(acc[mi][ni][2]), "+f"(acc[mi][ni][3])
                        : "r"(af[cur][mi][0]), "r"(af[cur][mi][1]),
                          "r"(af[cur][mi][2]), "r"(af[cur][mi][3]),
                          "r"(bf[cur][ni][0]), "r"(bf[cur][ni][1]));
        }
    }

    #pragma unroll
    for (int mi = 0; mi < 4; mi++) {
        int r0 = bm + wm + mi * 16 + g;
        #pragma unroll
        for (int ni = 0; ni < 4; ni++) {
            int c0 = bn + wn + ni * 8 + tg * 2;
            float bv0 = bias[c0], bv1 = bias[c0 + 1];
            float v0 = acc[mi][ni][0] + bv0;
            float v1 = acc[mi][ni][1] + bv1;
            float v2 = acc[mi][ni][2] + bv0;
            float v3 = acc[mi][ni][3] + bv1;
            if (relu) {
                v0 = fmaxf(v0, 0.f); v1 = fmaxf(v1, 0.f);
                v2 = fmaxf(v2, 0.f); v3 = fmaxf(v3, 0.f);
            }
            if (rnd) {
                v0 = f2tf32(v0); v1 = f2tf32(v1);
                v2 = f2tf32(v2); v3 = f2tf32(v3);
            }
            *(float2*)(C + (size_t)r0 * N + c0)       = make_float2(v0, v1);
            *(float2*)(C + (size_t)(r0 + 8) * N + c0) = make_float2(v2, v3);
        }
    }
}

// ---------------------------------------------------------------------------
__global__ __launch_bounds__(256)
void round_tf32(const float* __restrict__ src, float* __restrict__ dst)
{
    const size_t i = (size_t)blockIdx.x * blockDim.x + threadIdx.x;
    float4 v = ((const float4*)src)[i];
    v.x = f2tf32(v.x); v.y = f2tf32(v.y); v.z = f2tf32(v.z); v.w = f2tf32(v.w);
    ((float4*)dst)[i] = v;
}

// ---------------------------------------------------------------------------
// LayerNorm (+residual): x = [x +] LN(z)*g + b  (fp32, residual stream)
//                        xr = tf32_round(x)     (GEMM A-operand copy)
// ---------------------------------------------------------------------------
template <bool RES>
__global__ __launch_bounds__(256)
void ln_kernel(const float* __restrict__ z, float* __restrict__ x,
               float* __restrict__ xr,
               const float* __restrict__ gamma, const float* __restrict__ beta)
{
    const int row = blockIdx.x;
    const int t   = threadIdx.x;

    float4 v = ((const float4*)(z + (size_t)row * HDIM))[t];
    float s  = v.x + v.y + v.z + v.w;
    float ss = v.x * v.x + v.y * v.y + v.z * v.z + v.w * v.w;
    #pragma unroll
    for (int o = 16; o; o >>= 1) {
        s  += __shfl_xor_sync(0xffffffffu, s, o);
        ss += __shfl_xor_sync(0xffffffffu, ss, o);
    }
    __shared__ float sbuf[16];
    const int w = t >> 5, l = t & 31;
    if (l == 0) { sbuf[w] = s; sbuf[8 + w] = ss; }
    __syncthreads();
    float tot = 0.f, tot2 = 0.f;
    #pragma unroll
    for (int i = 0; i < 8; i++) { tot += sbuf[i]; tot2 += sbuf[8 + i]; }

    const float inv  = 1.f / (float)HDIM;
    const float mu   = tot * inv;
    const float var  = tot2 * inv - mu * mu;
    const float rstd = rsqrtf(var + 1e-5f);

    float4 gm = ((const float4*)gamma)[t];
    float4 bt = ((const float4*)beta)[t];
    float4 o;
    o.x = (v.x - mu) * rstd * gm.x + bt.x;
    o.y = (v.y - mu) * rstd * gm.y + bt.y;
    o.z = (v.z - mu) * rstd * gm.z + bt.z;
    o.w = (v.w - mu) * rstd * gm.w + bt.w;
    if (RES) {
        float4 xv = ((const float4*)(x + (size_t)row * HDIM))[t];
        o.x += xv.x; o.y += xv.y; o.z += xv.z; o.w += xv.w;
    }
    ((float4*)(x + (size_t)row * HDIM))[t] = o;        // fp32 residual
    float4 r;
    r.x = f2tf32(o.x); r.y = f2tf32(o.y); r.z = f2tf32(o.z); r.w = f2tf32(o.w);
    ((float4*)(xr + (size_t)row * HDIM))[t] = r;       // rounded GEMM input
}

// ---------------------------------------------------------------------------
__global__ __launch_bounds__(256)
void logits_kernel(const float* __restrict__ xe, const float* __restrict__ emb,
                   const int* __restrict__ idx, float* __restrict__ out)
{
    const int b = blockIdx.x;
    __shared__ float4 xs[EDIM / 4];
    const int t = threadIdx.x;
    if (t < EDIM / 4) xs[t] = ((const float4*)(xe + (size_t)b * EDIM))[t];
    __syncthreads();

    const int warp = t >> 5, lane = t & 31;
    for (int a = warp; a < ADIM; a += 8) {
        const float4* row = (const float4*)(emb + ((size_t)b * ADIM + a) * EDIM);
        float acc = 0.f;
        #pragma unroll
        for (int i = 0; i < 2; i++) {
            float4 v  = row[lane + 32 * i];
            float4 xv = xs[lane + 32 * i];
            acc += v.x * xv.x + v.y * xv.y + v.z * xv.z + v.w * xv.w;
        }
        #pragma unroll
        for (int o = 16; o; o >>= 1) acc += __shfl_xor_sync(0xffffffffu, acc, o);
        if (lane == 0) {
            int4 ii = ((const int4*)idx)[(size_t)b * ADIM + a];
            bool mask = (ii.x + ii.y + ii.z + ii.w) == 0;
            out[(size_t)b * ADIM + a] = mask ? __int_as_float(0xff800000) : acc;
        }
    }
}

// ---------------------------------------------------------------------------
extern "C" void kernel_launch(void* const* d_in, const int* in_sizes, int n_in,
                              void* d_out, int out_size)
{
    (void)in_sizes; (void)n_in; (void)out_size;
    const float* obs   = (const float*)d_in[0];
    const float* emb   = (const float*)d_in[1];
    const int*   idx   = (const int*)d_in[2];
    const float* w0    = (const float*)d_in[3];
    const float* b0    = (const float*)d_in[4];
    const float* g0    = (const float*)d_in[5];
    const float* be0   = (const float*)d_in[6];
    const float* Wb    = (const float*)d_in[7];
    const float* bb    = (const float*)d_in[8];
    const float* gb    = (const float*)d_in[9];
    const float* betab = (const float*)d_in[10];
    const float* w1    = (const float*)d_in[11];
    const float* b1    = (const float*)d_in[12];
    const float* w2    = (const float*)d_in[13];
    const float* b2    = (const float*)d_in[14];
    float* out = (float*)d_out;

    float *x, *xr, *z, *e, *a0, *wt;
    cudaGetSymbolAddress((void**)&x,  g_x);
    cudaGetSymbolAddress((void**)&xr, g_xr);
    cudaGetSymbolAddress((void**)&z,  g_z);
    cudaGetSymbolAddress((void**)&e,  g_e);
    cudaGetSymbolAddress((void**)&a0, g_a0);
    cudaGetSymbolAddress((void**)&wt, g_wt);
    float* wt0 = wt + WT0_OFF;
    float* wtb = wt + WTB_OFF;
    float* wt1 = wt + WT1_OFF;
    float* wt2 = wt + WT2_OFF;

    cudaFuncSetAttribute(gemm_pipe, cudaFuncAttributeMaxDynamicSharedMemorySize,
                         GEMM_SMEM_BYTES);

    const dim3 blk(256);

    // preprocess: tf32-round obs and all weights
    round_tf32<<<(BATCH * EDIM) / 1024, blk>>>(obs, a0);
    round_tf32<<<(EDIM * HDIM) / 1024, blk>>>(w0, wt0);
    round_tf32<<<(NLAYER * HDIM * HDIM) / 1024, blk>>>(Wb, wtb);
    round_tf32<<<(HDIM * HDIM) / 1024, blk>>>(w1, wt1);
    round_tf32<<<(HDIM * EDIM) / 1024, blk>>>(w2, wt2);

    const dim3 gridH(HDIM / 128, BATCH / 128);
    const dim3 gridE(EDIM / 128, BATCH / 128);

    // obs_transform
    gemm_pipe<<<gridH, blk, GEMM_SMEM_BYTES>>>(a0, wt0, b0, z, HDIM, EDIM, 1, 0);
    ln_kernel<false><<<BATCH, blk>>>(z, x, xr, g0, be0);

    // residual blocks
    for (int i = 0; i < NLAYER; i++) {
        gemm_pipe<<<gridH, blk, GEMM_SMEM_BYTES>>>(xr, wtb + (size_t)i * HDIM * HDIM,
                                                   bb + (size_t)i * HDIM, z,
                                                   HDIM, HDIM, 1, 0);
        ln_kernel<true><<<BATCH, blk>>>(z, x, xr, gb + (size_t)i * HDIM,
                                        betab + (size_t)i * HDIM);
    }

    // out_transform
    gemm_pipe<<<gridH, blk, GEMM_SMEM_BYTES>>>(xr, wt1, b1, z, HDIM, HDIM, 1, 1);
    gemm_pipe<<<gridE, blk, GEMM_SMEM_BYTES>>>(z, wt2, b2, e, EDIM, HDIM, 0, 0);

    // logits + mask
    logits_kernel<<<BATCH, blk>>>(e, emb, idx, out);
}

// round 6
// speedup vs baseline: 1.6964x; 1.2750x over previous
#include <cuda_runtime.h>
#include <cuda_fp16.h>
#include <cstdint>

#define BATCH 16384
#define EDIM  256
#define HDIM  1024
#define ADIM  256
#define NLAYER 8
#define STAGES 4

// ---------------- scratch (__device__ globals) -----------------------------
__device__ float  g_x [(size_t)BATCH * HDIM];   // fp32 residual stream
__device__ __half g_xr[(size_t)BATCH * HDIM];   // half GEMM A-operand copy
__device__ float  g_z [(size_t)BATCH * HDIM];   // pre-LN fp32
__device__ __half g_zh[(size_t)BATCH * HDIM];   // post-w1 half
__device__ float  g_e [(size_t)BATCH * EDIM];
__device__ __half g_a0[(size_t)BATCH * EDIM];
// half, transposed [N][K]: wt0 | wtb[8] | wt1 | wt2
#define WT0_OFF 0
#define WTB_OFF (WT0_OFF + (size_t)HDIM * EDIM)
#define WT1_OFF (WTB_OFF + (size_t)NLAYER * HDIM * HDIM)
#define WT2_OFF (WT1_OFF + (size_t)HDIM * HDIM)
__device__ __half g_wt[WT2_OFF + (size_t)EDIM * HDIM];

__device__ __forceinline__ uint32_t smem_u32(const void* p) {
    uint32_t a;
    asm("{ .reg .u64 t; cvta.to.shared.u64 t, %1; cvt.u32.u64 %0, t; }"
        : "=r"(a) : "l"(p));
    return a;
}
__device__ __forceinline__ void cp16(uint32_t dst, const void* src) {
    asm volatile("cp.async.cg.shared.global [%0], [%1], 16;" :: "r"(dst), "l"(src));
}
#define CP_COMMIT() asm volatile("cp.async.commit_group;" ::: "memory")
#define CP_WAIT2()  asm volatile("cp.async.wait_group 2;" ::: "memory")

// ---------------------------------------------------------------------------
// fp16 MMA GEMM: C[M,N] = act( A[M,K] @ Bt[N,K]^T + bias[N] )
// A: [M][K] half, Bt: [N][K] half. CTA tile 128x128x32, 4-stage cp.async.
// 256 threads, warp tile 64x32 (2x4 warp grid), mma m16n8k16.
// ---------------------------------------------------------------------------
#define AST 40                       // halves per smem row (conflict-free)
#define TILE_H (128 * AST)           // halves per A (or B) stage
#define GEMM_SMEM_BYTES (STAGES * 2 * TILE_H * 2)

template <int RELU, int OUTH>
__global__ __launch_bounds__(256, 2)
void gemm_h(const __half* __restrict__ A, const __half* __restrict__ Bt,
            const float* __restrict__ bias, float* __restrict__ Cf,
            __half* __restrict__ Ch, int N, int K)
{
    extern __shared__ __half sm[];
    __half* As = sm;                     // [STAGES][128][AST]
    __half* Bs = sm + STAGES * TILE_H;   // [STAGES][128][AST]
    const uint32_t sA = smem_u32(As);
    const uint32_t sB = smem_u32(Bs);

    const int tid  = threadIdx.x;
    const int warp = tid >> 5;
    const int lane = tid & 31;
    const int wm = (warp & 1) * 64;
    const int wn = (warp >> 1) * 32;
    const int g  = lane >> 2;
    const int tg = lane & 3;

    const int bm = blockIdx.y * 128;
    const int bn = blockIdx.x * 128;
    const int ns = K >> 5;

    float acc[4][4][4];
    #pragma unroll
    for (int i = 0; i < 4; i++)
        #pragma unroll
        for (int j = 0; j < 4; j++)
            #pragma unroll
            for (int r = 0; r < 4; r++) acc[i][j][r] = 0.f;

    // per stage: A 128 rows x 32 halves (64B = 4 chunks), B same -> 2+2 cp16/thr
    auto load_stage = [&](int s, int buf) {
        const int k0 = s << 5;
        #pragma unroll
        for (int i = 0; i < 2; i++) {
            int f = tid + i * 256;               // 0..511
            int row = f >> 2, ch = f & 3;
            cp16(sA + (buf * TILE_H + row * AST + ch * 8) * 2,
                 A + (size_t)(bm + row) * K + k0 + ch * 8);
        }
        #pragma unroll
        for (int i = 0; i < 2; i++) {
            int f = tid + i * 256;
            int row = f >> 2, ch = f & 3;
            cp16(sB + (buf * TILE_H + row * AST + ch * 8) * 2,
                 Bt + (size_t)(bn + row) * K + k0 + ch * 8);
        }
    };

    #pragma unroll
    for (int s = 0; s < STAGES - 1; s++) {
        load_stage(s, s);
        CP_COMMIT();
    }
    CP_WAIT2();
    __syncthreads();

    for (int s = 0; s < ns; s++) {
        const int buf = s & (STAGES - 1);
        if (s + STAGES - 1 < ns)
            load_stage(s + STAGES - 1, (s + STAGES - 1) & (STAGES - 1));
        CP_COMMIT();

        const __half* ab = As + buf * TILE_H;
        const __half* bb = Bs + buf * TILE_H;
        #pragma unroll
        for (int kk = 0; kk < 32; kk += 16) {
            uint32_t a[4][4], b[4][2];
            #pragma unroll
            for (int mi = 0; mi < 4; mi++) {
                int r = wm + mi * 16 + g;
                a[mi][0] = *(const uint32_t*)(ab + (r    ) * AST + kk + tg * 2);
                a[mi][1] = *(const uint32_t*)(ab + (r + 8) * AST + kk + tg * 2);
                a[mi][2] = *(const uint32_t*)(ab + (r    ) * AST + kk + tg * 2 + 8);
                a[mi][3] = *(const uint32_t*)(ab + (r + 8) * AST + kk + tg * 2 + 8);
            }
            #pragma unroll
            for (int ni = 0; ni < 4; ni++) {
                int c = wn + ni * 8 + g;
                b[ni][0] = *(const uint32_t*)(bb + c * AST + kk + tg * 2);
                b[ni][1] = *(const uint32_t*)(bb + c * AST + kk + tg * 2 + 8);
            }
            #pragma unroll
            for (int mi = 0; mi < 4; mi++)
                #pragma unroll
                for (int ni = 0; ni < 4; ni++)
                    asm volatile(
                        "mma.sync.aligned.m16n8k16.row.col.f32.f16.f16.f32 "
                        "{%0,%1,%2,%3},{%4,%5,%6,%7},{%8,%9},{%0,%1,%2,%3};"
                        : "+f"(acc[mi][ni][0]), "+f"(acc[mi][ni][1]),
                          "+f"(acc[mi][ni][2]), "+f"(acc[mi][ni][3])
                        : "r"(a[mi][0]), "r"(a[mi][1]),
                          "r"(a[mi][2]), "r"(a[mi][3]),
                          "r"(b[ni][0]), "r"(b[ni][1]));
        }
        CP_WAIT2();
        __syncthreads();
    }

    // epilogue: bias (+ReLU); fp32 or half store
    #pragma unroll
    for (int mi = 0; mi < 4; mi++) {
        int r0 = bm + wm + mi * 16 + g;
        #pragma unroll
        for (int ni = 0; ni < 4; ni++) {
            int c0 = bn + wn + ni * 8 + tg * 2;
            float bv0 = bias[c0], bv1 = bias[c0 + 1];
            float v0 = acc[mi][ni][0] + bv0;
            float v1 = acc[mi][ni][1] + bv1;
            float v2 = acc[mi][ni][2] + bv0;
            float v3 = acc[mi][ni][3] + bv1;
            if (RELU) {
                v0 = fmaxf(v0, 0.f); v1 = fmaxf(v1, 0.f);
                v2 = fmaxf(v2, 0.f); v3 = fmaxf(v3, 0.f);
            }
            if (OUTH) {
                *(half2*)(Ch + (size_t)r0 * N + c0)       = __floats2half2_rn(v0, v1);
                *(half2*)(Ch + (size_t)(r0 + 8) * N + c0) = __floats2half2_rn(v2, v3);
            } else {
                *(float2*)(Cf + (size_t)r0 * N + c0)       = make_float2(v0, v1);
                *(float2*)(Cf + (size_t)(r0 + 8) * N + c0) = make_float2(v2, v3);
            }
        }
    }
}

// ---------------------------------------------------------------------------
// fp32 -> half elementwise (count % 2048 == 0)
// ---------------------------------------------------------------------------
__global__ __launch_bounds__(256)
void cvt_half(const float* __restrict__ src, __half* __restrict__ dst)
{
    const size_t i = (size_t)blockIdx.x * blockDim.x + threadIdx.x;
    float4 v = ((const float4*)src)[i];
    half2 h0 = __floats2half2_rn(v.x, v.y);
    half2 h1 = __floats2half2_rn(v.z, v.w);
    ((half2*)dst)[i * 2]     = h0;
    ((half2*)dst)[i * 2 + 1] = h1;
}

// ---------------------------------------------------------------------------
// transpose fp32[K][N] -> half dst[N][K]
// ---------------------------------------------------------------------------
__global__ __launch_bounds__(256)
void transpose_h(const float* __restrict__ src, __half* __restrict__ dst,
                 int K, int N)
{
    __shared__ float t[32][33];
    const int n0 = blockIdx.x * 32, k0 = blockIdx.y * 32;
    const int tx = threadIdx.x, ty = threadIdx.y;
    #pragma unroll
    for (int i = 0; i < 32; i += 8)
        t[ty + i][tx] = src[(size_t)(k0 + ty + i) * N + n0 + tx];
    __syncthreads();
    #pragma unroll
    for (int i = 0; i < 32; i += 8)
        dst[(size_t)(n0 + ty + i) * K + k0 + tx] = __float2half_rn(t[tx][ty + i]);
}

// ---------------------------------------------------------------------------
// LayerNorm (+residual): x = [x +] LN(z)*g + b (fp32); xr = half(x)
// ---------------------------------------------------------------------------
template <bool RES>
__global__ __launch_bounds__(256)
void ln_kernel(const float* __restrict__ z, float* __restrict__ x,
               __half* __restrict__ xr,
               const float* __restrict__ gamma, const float* __restrict__ beta)
{
    const int row = blockIdx.x;
    const int t   = threadIdx.x;

    float4 v = ((const float4*)(z + (size_t)row * HDIM))[t];
    float s  = v.x + v.y + v.z + v.w;
    float ss = v.x * v.x + v.y * v.y + v.z * v.z + v.w * v.w;
    #pragma unroll
    for (int o = 16; o; o >>= 1) {
        s  += __shfl_xor_sync(0xffffffffu, s, o);
        ss += __shfl_xor_sync(0xffffffffu, ss, o);
    }
    __shared__ float sbuf[16];
    const int w = t >> 5, l = t & 31;
    if (l == 0) { sbuf[w] = s; sbuf[8 + w] = ss; }
    __syncthreads();
    float tot = 0.f, tot2 = 0.f;
    #pragma unroll
    for (int i = 0; i < 8; i++) { tot += sbuf[i]; tot2 += sbuf[8 + i]; }

    const float inv  = 1.f / (float)HDIM;
    const float mu   = tot * inv;
    const float var  = tot2 * inv - mu * mu;
    const float rstd = rsqrtf(var + 1e-5f);

    float4 gm = ((const float4*)gamma)[t];
    float4 bt = ((const float4*)beta)[t];
    float4 o;
    o.x = (v.x - mu) * rstd * gm.x + bt.x;
    o.y = (v.y - mu) * rstd * gm.y + bt.y;
    o.z = (v.z - mu) * rstd * gm.z + bt.z;
    o.w = (v.w - mu) * rstd * gm.w + bt.w;
    if (RES) {
        float4 xv = ((const float4*)(x + (size_t)row * HDIM))[t];
        o.x += xv.x; o.y += xv.y; o.z += xv.z; o.w += xv.w;
    }
    ((float4*)(x + (size_t)row * HDIM))[t] = o;
    half2 h0 = __floats2half2_rn(o.x, o.y);
    half2 h1 = __floats2half2_rn(o.z, o.w);
    ((half2*)(xr + (size_t)row * HDIM))[t * 2]     = h0;
    ((half2*)(xr + (size_t)row * HDIM))[t * 2 + 1] = h1;
}

// ---------------------------------------------------------------------------
// logits[b,a] = dot(xe[b], emb[b,a]); masked -> -inf
// ---------------------------------------------------------------------------
__global__ __launch_bounds__(256)
void logits_kernel(const float* __restrict__ xe, const float* __restrict__ emb,
                   const int* __restrict__ idx, float* __restrict__ out)
{
    const int b = blockIdx.x;
    __shared__ float4 xs[EDIM / 4];
    const int t = threadIdx.x;
    if (t < EDIM / 4) xs[t] = ((const float4*)(xe + (size_t)b * EDIM))[t];
    __syncthreads();

    const int warp = t >> 5, lane = t & 31;
    for (int a = warp; a < ADIM; a += 8) {
        const float4* row = (const float4*)(emb + ((size_t)b * ADIM + a) * EDIM);
        float acc = 0.f;
        #pragma unroll
        for (int i = 0; i < 2; i++) {
            float4 v  = row[lane + 32 * i];
            float4 xv = xs[lane + 32 * i];
            acc += v.x * xv.x + v.y * xv.y + v.z * xv.z + v.w * xv.w;
        }
        #pragma unroll
        for (int o = 16; o; o >>= 1) acc += __shfl_xor_sync(0xffffffffu, acc, o);
        if (lane == 0) {
            int4 ii = ((const int4*)idx)[(size_t)b * ADIM + a];
            bool mask = (ii.x + ii.y + ii.z + ii.w) == 0;
            out[(size_t)b * ADIM + a] = mask ? __int_as_float(0xff800000) : acc;
        }
    }
}

// ---------------------------------------------------------------------------
extern "C" void kernel_launch(void* const* d_in, const int* in_sizes, int n_in,
                              void* d_out, int out_size)
{
    (void)in_sizes; (void)n_in; (void)out_size;
    const float* obs   = (const float*)d_in[0];
    const float* emb   = (const float*)d_in[1];
    const int*   idx   = (const int*)d_in[2];
    const float* w0    = (const float*)d_in[3];
    const float* b0    = (const float*)d_in[4];
    const float* g0    = (const float*)d_in[5];
    const float* be0   = (const float*)d_in[6];
    const float* Wb    = (const float*)d_in[7];
    const float* bb    = (const float*)d_in[8];
    const float* gb    = (const float*)d_in[9];
    const float* betab = (const float*)d_in[10];
    const float* w1    = (const float*)d_in[11];
    const float* b1    = (const float*)d_in[12];
    const float* w2    = (const float*)d_in[13];
    const float* b2    = (const float*)d_in[14];
    float* out = (float*)d_out;

    float  *x, *z, *e;
    __half *xr, *zh, *a0, *wt;
    cudaGetSymbolAddress((void**)&x,  g_x);
    cudaGetSymbolAddress((void**)&xr, g_xr);
    cudaGetSymbolAddress((void**)&z,  g_z);
    cudaGetSymbolAddress((void**)&zh, g_zh);
    cudaGetSymbolAddress((void**)&e,  g_e);
    cudaGetSymbolAddress((void**)&a0, g_a0);
    cudaGetSymbolAddress((void**)&wt, g_wt);
    __half* wt0 = wt + WT0_OFF;
    __half* wtb = wt + WTB_OFF;
    __half* wt1 = wt + WT1_OFF;
    __half* wt2 = wt + WT2_OFF;

    cudaFuncSetAttribute(gemm_h<1, 0>, cudaFuncAttributeMaxDynamicSharedMemorySize,
                         GEMM_SMEM_BYTES);
    cudaFuncSetAttribute(gemm_h<1, 1>, cudaFuncAttributeMaxDynamicSharedMemorySize,
                         GEMM_SMEM_BYTES);
    cudaFuncSetAttribute(gemm_h<0, 0>, cudaFuncAttributeMaxDynamicSharedMemorySize,
                         GEMM_SMEM_BYTES);

    const dim3 blk(256);
    const dim3 tblk(32, 8);

    // preprocess: obs -> half; weights -> transposed half [N][K]
    cvt_half<<<(BATCH * EDIM) / 1024, blk>>>(obs, a0);
    transpose_h<<<dim3(HDIM / 32, EDIM / 32), tblk>>>(w0, wt0, EDIM, HDIM);
    for (int i = 0; i < NLAYER; i++)
        transpose_h<<<dim3(HDIM / 32, HDIM / 32), tblk>>>(
            Wb + (size_t)i * HDIM * HDIM, wtb + (size_t)i * HDIM * HDIM, HDIM, HDIM);
    transpose_h<<<dim3(HDIM / 32, HDIM / 32), tblk>>>(w1, wt1, HDIM, HDIM);
    transpose_h<<<dim3(EDIM / 32, HDIM / 32), tblk>>>(w2, wt2, HDIM, EDIM);

    const dim3 gridH(HDIM / 128, BATCH / 128);   // (8, 128)
    const dim3 gridE(EDIM / 128, BATCH / 128);   // (2, 128)

    // obs_transform
    gemm_h<1, 0><<<gridH, blk, GEMM_SMEM_BYTES>>>(a0, wt0, b0, z, nullptr,
                                                  HDIM, EDIM);
    ln_kernel<false><<<BATCH, blk>>>(z, x, xr, g0, be0);

    // residual blocks
    for (int i = 0; i < NLAYER; i++) {
        gemm_h<1, 0><<<gridH, blk, GEMM_SMEM_BYTES>>>(
            xr, wtb + (size_t)i * HDIM * HDIM, bb + (size_t)i * HDIM, z, nullptr,
            HDIM, HDIM);
        ln_kernel<true><<<BATCH, blk>>>(z, x, xr, gb + (size_t)i * HDIM,
                                        betab + (size_t)i * HDIM);
    }

    // out_transform: zh = half(relu(x@w1+b1)); e = zh@w2 + b2
    gemm_h<1, 1><<<gridH, blk, GEMM_SMEM_BYTES>>>(xr, wt1, b1, nullptr, zh,
                                                  HDIM, HDIM);
    gemm_h<0, 0><<<gridE, blk, GEMM_SMEM_BYTES>>>(zh, wt2, b2, e, nullptr,
                                                  EDIM, HDIM);

    // logits + mask
    logits_kernel<<<BATCH, blk>>>(e, emb, idx, out);
}

// round 7
// speedup vs baseline: 1.7926x; 1.0567x over previous
#include <cuda_runtime.h>
#include <cuda_fp16.h>
#include <cstdint>

#define BATCH 16384
#define EDIM  256
#define HDIM  1024
#define ADIM  256
#define NLAYER 8
#define STAGES 4

// ---------------- scratch (__device__ globals) -----------------------------
__device__ float  g_x [(size_t)BATCH * HDIM];   // fp32 residual stream
__device__ __half g_xr[(size_t)BATCH * HDIM];   // half GEMM A-operand copy
__device__ float  g_z [(size_t)BATCH * HDIM];   // pre-LN fp32
__device__ __half g_zh[(size_t)BATCH * HDIM];   // post-w1 half
__device__ float  g_e [(size_t)BATCH * EDIM];
__device__ __half g_a0[(size_t)BATCH * EDIM];
// half, transposed [N][K]: wt0 | wtb[8] | wt1 | wt2
#define WT0_OFF 0
#define WTB_OFF (WT0_OFF + (size_t)HDIM * EDIM)
#define WT1_OFF (WTB_OFF + (size_t)NLAYER * HDIM * HDIM)
#define WT2_OFF (WT1_OFF + (size_t)HDIM * HDIM)
__device__ __half g_wt[WT2_OFF + (size_t)EDIM * HDIM];

__device__ __forceinline__ uint32_t smem_u32(const void* p) {
    uint32_t a;
    asm("{ .reg .u64 t; cvta.to.shared.u64 t, %1; cvt.u32.u64 %0, t; }"
        : "=r"(a) : "l"(p));
    return a;
}
__device__ __forceinline__ void cp16(uint32_t dst, const void* src) {
    asm volatile("cp.async.cg.shared.global [%0], [%1], 16;" :: "r"(dst), "l"(src));
}
__device__ __forceinline__ void ldsm4(uint32_t& r0, uint32_t& r1,
                                      uint32_t& r2, uint32_t& r3, uint32_t addr) {
    asm volatile("ldmatrix.sync.aligned.m8n8.x4.shared.b16 {%0,%1,%2,%3}, [%4];"
                 : "=r"(r0), "=r"(r1), "=r"(r2), "=r"(r3) : "r"(addr));
}
#define CP_COMMIT() asm volatile("cp.async.commit_group;" ::: "memory")
#define CP_WAIT2()  asm volatile("cp.async.wait_group 2;" ::: "memory")

// ---------------------------------------------------------------------------
// fp16 MMA GEMM: C[M,N] = act( A[M,K] @ Bt[N,K]^T + bias[N] )
// CTA 128x128x32, 4-stage cp.async, 8 warps @ 64x32, ldmatrix fragment loads.
// ---------------------------------------------------------------------------
#define AST 40                       // halves per smem row (conflict-free)
#define TILE_H (128 * AST)
#define GEMM_SMEM_BYTES (STAGES * 2 * TILE_H * 2)

template <int RELU, int OUTH>
__global__ __launch_bounds__(256, 2)
void gemm_h(const __half* __restrict__ A, const __half* __restrict__ Bt,
            const float* __restrict__ bias, float* __restrict__ Cf,
            __half* __restrict__ Ch, int N, int K)
{
    extern __shared__ __half sm[];
    __half* As = sm;                     // [STAGES][128][AST]
    __half* Bs = sm + STAGES * TILE_H;   // [STAGES][128][AST]
    const uint32_t sA = smem_u32(As);
    const uint32_t sB = smem_u32(Bs);

    const int tid  = threadIdx.x;
    const int warp = tid >> 5;
    const int lane = tid & 31;
    const int wm = (warp & 1) * 64;
    const int wn = (warp >> 1) * 32;
    const int g  = lane >> 2;
    const int tg = lane & 3;

    const int bm = blockIdx.y * 128;
    const int bn = blockIdx.x * 128;
    const int ns = K >> 5;

    // ldmatrix per-lane address offsets (in halves, within a stage)
    // A x4: matrices {r0-7 k0-7, r8-15 k0-7, r0-7 k8-15, r8-15 k8-15}
    const int a_off = (wm + (lane & 7) + ((lane >> 3) & 1) * 8) * AST
                    + (lane >> 4) * 8;
    // B x4: matrices {n0-7 k0-7, n0-7 k8-15, n8-15 k0-7, n8-15 k8-15}
    const int b_off = (wn + (lane & 7) + (lane >> 4) * 8) * AST
                    + ((lane >> 3) & 1) * 8;

    float acc[4][4][4];
    #pragma unroll
    for (int i = 0; i < 4; i++)
        #pragma unroll
        for (int j = 0; j < 4; j++)
            #pragma unroll
            for (int r = 0; r < 4; r++) acc[i][j][r] = 0.f;

    auto load_stage = [&](int s, int buf) {
        const int k0 = s << 5;
        #pragma unroll
        for (int i = 0; i < 2; i++) {
            int f = tid + i * 256;               // 0..511
            int row = f >> 2, ch = f & 3;
            cp16(sA + (buf * TILE_H + row * AST + ch * 8) * 2,
                 A + (size_t)(bm + row) * K + k0 + ch * 8);
        }
        #pragma unroll
        for (int i = 0; i < 2; i++) {
            int f = tid + i * 256;
            int row = f >> 2, ch = f & 3;
            cp16(sB + (buf * TILE_H + row * AST + ch * 8) * 2,
                 Bt + (size_t)(bn + row) * K + k0 + ch * 8);
        }
    };

    #pragma unroll
    for (int s = 0; s < STAGES - 1; s++) {
        load_stage(s, s);
        CP_COMMIT();
    }
    CP_WAIT2();
    __syncthreads();

    for (int s = 0; s < ns; s++) {
        const int buf = s & (STAGES - 1);
        if (s + STAGES - 1 < ns)
            load_stage(s + STAGES - 1, (s + STAGES - 1) & (STAGES - 1));
        CP_COMMIT();

        const uint32_t abB = sA + (buf * TILE_H + a_off) * 2;
        const uint32_t bbB = sB + (buf * TILE_H + b_off) * 2;
        #pragma unroll
        for (int kk = 0; kk < 32; kk += 16) {
            uint32_t a[4][4], b[2][4];
            #pragma unroll
            for (int mi = 0; mi < 4; mi++)
                ldsm4(a[mi][0], a[mi][1], a[mi][2], a[mi][3],
                      abB + (mi * 16 * AST + kk) * 2);
            #pragma unroll
            for (int np = 0; np < 2; np++)
                ldsm4(b[np][0], b[np][1], b[np][2], b[np][3],
                      bbB + (np * 16 * AST + kk) * 2);
            #pragma unroll
            for (int mi = 0; mi < 4; mi++)
                #pragma unroll
                for (int ni = 0; ni < 4; ni++)
                    asm volatile(
                        "mma.sync.aligned.m16n8k16.row.col.f32.f16.f16.f32 "
                        "{%0,%1,%2,%3},{%4,%5,%6,%7},{%8,%9},{%0,%1,%2,%3};"
                        : "+f"(acc[mi][ni][0]), "+f"(acc[mi][ni][1]),
                          "+f"(acc[mi][ni][2]), "+f"(acc[mi][ni][3])
                        : "r"(a[mi][0]), "r"(a[mi][1]),
                          "r"(a[mi][2]), "r"(a[mi][3]),
                          "r"(b[ni >> 1][(ni & 1) * 2]),
                          "r"(b[ni >> 1][(ni & 1) * 2 + 1]));
        }
        CP_WAIT2();
        __syncthreads();
    }

    // epilogue: bias (+ReLU); fp32 or half store
    #pragma unroll
    for (int mi = 0; mi < 4; mi++) {
        int r0 = bm + wm + mi * 16 + g;
        #pragma unroll
        for (int ni = 0; ni < 4; ni++) {
            int c0 = bn + wn + ni * 8 + tg * 2;
            float bv0 = bias[c0], bv1 = bias[c0 + 1];
            float v0 = acc[mi][ni][0] + bv0;
            float v1 = acc[mi][ni][1] + bv1;
            float v2 = acc[mi][ni][2] + bv0;
            float v3 = acc[mi][ni][3] + bv1;
            if (RELU) {
                v0 = fmaxf(v0, 0.f); v1 = fmaxf(v1, 0.f);
                v2 = fmaxf(v2, 0.f); v3 = fmaxf(v3, 0.f);
            }
            if (OUTH) {
                *(half2*)(Ch + (size_t)r0 * N + c0)       = __floats2half2_rn(v0, v1);
                *(half2*)(Ch + (size_t)(r0 + 8) * N + c0) = __floats2half2_rn(v2, v3);
            } else {
                *(float2*)(Cf + (size_t)r0 * N + c0)       = make_float2(v0, v1);
                *(float2*)(Cf + (size_t)(r0 + 8) * N + c0) = make_float2(v2, v3);
            }
        }
    }
}

// ---------------------------------------------------------------------------
__global__ __launch_bounds__(256)
void cvt_half(const float* __restrict__ src, __half* __restrict__ dst)
{
    const size_t i = (size_t)blockIdx.x * blockDim.x + threadIdx.x;
    float4 v = ((const float4*)src)[i];
    ((half2*)dst)[i * 2]     = __floats2half2_rn(v.x, v.y);
    ((half2*)dst)[i * 2 + 1] = __floats2half2_rn(v.z, v.w);
}

__global__ __launch_bounds__(256)
void transpose_h(const float* __restrict__ src, __half* __restrict__ dst,
                 int K, int N)
{
    __shared__ float t[32][33];
    const int n0 = blockIdx.x * 32, k0 = blockIdx.y * 32;
    const int tx = threadIdx.x, ty = threadIdx.y;
    #pragma unroll
    for (int i = 0; i < 32; i += 8)
        t[ty + i][tx] = src[(size_t)(k0 + ty + i) * N + n0 + tx];
    __syncthreads();
    #pragma unroll
    for (int i = 0; i < 32; i += 8)
        dst[(size_t)(n0 + ty + i) * K + k0 + tx] = __float2half_rn(t[tx][ty + i]);
}

// ---------------------------------------------------------------------------
// LayerNorm (+residual): x = [x +] LN(z)*g + b (fp32); xr = half(x)
// ---------------------------------------------------------------------------
template <bool RES>
__global__ __launch_bounds__(256)
void ln_kernel(const float* __restrict__ z, float* __restrict__ x,
               __half* __restrict__ xr,
               const float* __restrict__ gamma, const float* __restrict__ beta)
{
    const int row = blockIdx.x;
    const int t   = threadIdx.x;

    float4 v = ((const float4*)(z + (size_t)row * HDIM))[t];
    float s  = v.x + v.y + v.z + v.w;
    float ss = v.x * v.x + v.y * v.y + v.z * v.z + v.w * v.w;
    #pragma unroll
    for (int o = 16; o; o >>= 1) {
        s  += __shfl_xor_sync(0xffffffffu, s, o);
        ss += __shfl_xor_sync(0xffffffffu, ss, o);
    }
    __shared__ float sbuf[16];
    const int w = t >> 5, l = t & 31;
    if (l == 0) { sbuf[w] = s; sbuf[8 + w] = ss; }
    __syncthreads();
    float tot = 0.f, tot2 = 0.f;
    #pragma unroll
    for (int i = 0; i < 8; i++) { tot += sbuf[i]; tot2 += sbuf[8 + i]; }

    const float inv  = 1.f / (float)HDIM;
    const float mu   = tot * inv;
    const float var  = tot2 * inv - mu * mu;
    const float rstd = rsqrtf(var + 1e-5f);

    float4 gm = ((const float4*)gamma)[t];
    float4 bt = ((const float4*)beta)[t];
    float4 o;
    o.x = (v.x - mu) * rstd * gm.x + bt.x;
    o.y = (v.y - mu) * rstd * gm.y + bt.y;
    o.z = (v.z - mu) * rstd * gm.z + bt.z;
    o.w = (v.w - mu) * rstd * gm.w + bt.w;
    if (RES) {
        float4 xv = ((const float4*)(x + (size_t)row * HDIM))[t];
        o.x += xv.x; o.y += xv.y; o.z += xv.z; o.w += xv.w;
    }
    ((float4*)(x + (size_t)row * HDIM))[t] = o;
    ((half2*)(xr + (size_t)row * HDIM))[t * 2]     = __floats2half2_rn(o.x, o.y);
    ((half2*)(xr + (size_t)row * HDIM))[t * 2 + 1] = __floats2half2_rn(o.z, o.w);
}

// ---------------------------------------------------------------------------
// logits[b,a] = dot(xe[b], emb[b,a]); 4 actions per warp iteration (MLP=8)
// ---------------------------------------------------------------------------
__global__ __launch_bounds__(256)
void logits_kernel(const float* __restrict__ xe, const float* __restrict__ emb,
                   const int* __restrict__ idx, float* __restrict__ out)
{
    const int b = blockIdx.x;
    __shared__ float4 xs[EDIM / 4];
    const int t = threadIdx.x;
    if (t < EDIM / 4) xs[t] = ((const float4*)(xe + (size_t)b * EDIM))[t];
    __syncthreads();

    const int warp = t >> 5, lane = t & 31;
    const float4* ebase = (const float4*)(emb + (size_t)b * ADIM * EDIM);

    #pragma unroll
    for (int a0 = warp * 4; a0 < ADIM; a0 += 32) {
        float acc[4] = {0.f, 0.f, 0.f, 0.f};
        #pragma unroll
        for (int i = 0; i < 2; i++) {
            float4 xv = xs[lane + 32 * i];
            #pragma unroll
            for (int j = 0; j < 4; j++) {
                float4 v = ebase[(size_t)(a0 + j) * (EDIM / 4) + lane + 32 * i];
                acc[j] += v.x * xv.x + v.y * xv.y + v.z * xv.z + v.w * xv.w;
            }
        }
        #pragma unroll
        for (int o = 16; o; o >>= 1) {
            acc[0] += __shfl_xor_sync(0xffffffffu, acc[0], o);
            acc[1] += __shfl_xor_sync(0xffffffffu, acc[1], o);
            acc[2] += __shfl_xor_sync(0xffffffffu, acc[2], o);
            acc[3] += __shfl_xor_sync(0xffffffffu, acc[3], o);
        }
        if (lane < 4) {
            int a = a0 + lane;
            int4 ii = ((const int4*)idx)[(size_t)b * ADIM + a];
            bool mask = (ii.x + ii.y + ii.z + ii.w) == 0;
            out[(size_t)b * ADIM + a] = mask ? __int_as_float(0xff800000)
                                             : acc[lane];
        }
    }
}

// ---------------------------------------------------------------------------
extern "C" void kernel_launch(void* const* d_in, const int* in_sizes, int n_in,
                              void* d_out, int out_size)
{
    (void)in_sizes; (void)n_in; (void)out_size;
    const float* obs   = (const float*)d_in[0];
    const float* emb   = (const float*)d_in[1];
    const int*   idx   = (const int*)d_in[2];
    const float* w0    = (const float*)d_in[3];
    const float* b0    = (const float*)d_in[4];
    const float* g0    = (const float*)d_in[5];
    const float* be0   = (const float*)d_in[6];
    const float* Wb    = (const float*)d_in[7];
    const float* bb    = (const float*)d_in[8];
    const float* gb    = (const float*)d_in[9];
    const float* betab = (const float*)d_in[10];
    const float* w1    = (const float*)d_in[11];
    const float* b1    = (const float*)d_in[12];
    const float* w2    = (const float*)d_in[13];
    const float* b2    = (const float*)d_in[14];
    float* out = (float*)d_out;

    float  *x, *z, *e;
    __half *xr, *zh, *a0, *wt;
    cudaGetSymbolAddress((void**)&x,  g_x);
    cudaGetSymbolAddress((void**)&xr, g_xr);
    cudaGetSymbolAddress((void**)&z,  g_z);
    cudaGetSymbolAddress((void**)&zh, g_zh);
    cudaGetSymbolAddress((void**)&e,  g_e);
    cudaGetSymbolAddress((void**)&a0, g_a0);
    cudaGetSymbolAddress((void**)&wt, g_wt);
    __half* wt0 = wt + WT0_OFF;
    __half* wtb = wt + WTB_OFF;
    __half* wt1 = wt + WT1_OFF;
    __half* wt2 = wt + WT2_OFF;

    cudaFuncSetAttribute(gemm_h<1, 0>, cudaFuncAttributeMaxDynamicSharedMemorySize,
                         GEMM_SMEM_BYTES);
    cudaFuncSetAttribute(gemm_h<1, 1>, cudaFuncAttributeMaxDynamicSharedMemorySize,
                         GEMM_SMEM_BYTES);
    cudaFuncSetAttribute(gemm_h<0, 0>, cudaFuncAttributeMaxDynamicSharedMemorySize,
                         GEMM_SMEM_BYTES);

    const dim3 blk(256);
    const dim3 tblk(32, 8);

    cvt_half<<<(BATCH * EDIM) / 1024, blk>>>(obs, a0);
    transpose_h<<<dim3(HDIM / 32, EDIM / 32), tblk>>>(w0, wt0, EDIM, HDIM);
    for (int i = 0; i < NLAYER; i++)
        transpose_h<<<dim3(HDIM / 32, HDIM / 32), tblk>>>(
            Wb + (size_t)i * HDIM * HDIM, wtb + (size_t)i * HDIM * HDIM, HDIM, HDIM);
    transpose_h<<<dim3(HDIM / 32, HDIM / 32), tblk>>>(w1, wt1, HDIM, HDIM);
    transpose_h<<<dim3(EDIM / 32, HDIM / 32), tblk>>>(w2, wt2, HDIM, EDIM);

    const dim3 gridH(HDIM / 128, BATCH / 128);
    const dim3 gridE(EDIM / 128, BATCH / 128);

    gemm_h<1, 0><<<gridH, blk, GEMM_SMEM_BYTES>>>(a0, wt0, b0, z, nullptr,
                                                  HDIM, EDIM);
    ln_kernel<false><<<BATCH, blk>>>(z, x, xr, g0, be0);

    for (int i = 0; i < NLAYER; i++) {
        gemm_h<1, 0><<<gridH, blk, GEMM_SMEM_BYTES>>>(
            xr, wtb + (size_t)i * HDIM * HDIM, bb + (size_t)i * HDIM, z, nullptr,
            HDIM, HDIM);
        ln_kernel<true><<<BATCH, blk>>>(z, x, xr, gb + (size_t)i * HDIM,
                                        betab + (size_t)i * HDIM);
    }

    gemm_h<1, 1><<<gridH, blk, GEMM_SMEM_BYTES>>>(xr, wt1, b1, nullptr, zh,
                                                  HDIM, HDIM);
    gemm_h<0, 0><<<gridE, blk, GEMM_SMEM_BYTES>>>(zh, wt2, b2, e, nullptr,
                                                  EDIM, HDIM);

    logits_kernel<<<BATCH, blk>>>(e, emb, idx, out);
}

// round 8
// speedup vs baseline: 1.9194x; 1.0708x over previous
#include <cuda_runtime.h>
#include <cuda_fp16.h>
#include <cstdint>

#define BATCH 16384
#define EDIM  256
#define HDIM  1024
#define ADIM  256
#define NLAYER 8
#define STAGES 4

// ---------------- scratch (__device__ globals) -----------------------------
__device__ float  g_x [(size_t)BATCH * HDIM];   // fp32 residual stream
__device__ __half g_xr[(size_t)BATCH * HDIM];   // half GEMM A-operand copy
__device__ float  g_z [(size_t)BATCH * HDIM];   // pre-LN fp32
__device__ __half g_zh[(size_t)BATCH * HDIM];   // post-w1 half
__device__ float  g_e [(size_t)BATCH * EDIM];
__device__ __half g_a0[(size_t)BATCH * EDIM];
// half, transposed [N][K]: wt0 | wtb[8] | wt1 | wt2
#define WT0_OFF 0
#define WTB_OFF (WT0_OFF + (size_t)HDIM * EDIM)
#define WT1_OFF (WTB_OFF + (size_t)NLAYER * HDIM * HDIM)
#define WT2_OFF (WT1_OFF + (size_t)HDIM * HDIM)
__device__ __half g_wt[WT2_OFF + (size_t)EDIM * HDIM];

__device__ __forceinline__ uint32_t smem_u32(const void* p) {
    uint32_t a;
    asm("{ .reg .u64 t; cvta.to.shared.u64 t, %1; cvt.u32.u64 %0, t; }"
        : "=r"(a) : "l"(p));
    return a;
}
__device__ __forceinline__ void cp16(uint32_t dst, const void* src) {
    asm volatile("cp.async.cg.shared.global [%0], [%1], 16;" :: "r"(dst), "l"(src));
}
__device__ __forceinline__ void ldsm4(uint32_t& r0, uint32_t& r1,
                                      uint32_t& r2, uint32_t& r3, uint32_t addr) {
    asm volatile("ldmatrix.sync.aligned.m8n8.x4.shared.b16 {%0,%1,%2,%3}, [%4];"
                 : "=r"(r0), "=r"(r1), "=r"(r2), "=r"(r3) : "r"(addr));
}
#define CP_COMMIT() asm volatile("cp.async.commit_group;" ::: "memory")
#define CP_WAIT2()  asm volatile("cp.async.wait_group 2;" ::: "memory")

// ---------------------------------------------------------------------------
// fp16 MMA GEMM: C[M,N] = act( A[M,K] @ Bt[N,K]^T + bias[N] )
// CTA 128x128x32, 128 threads (4 warps @ 64x64), 2 CTAs/SM, 4-stage cp.async.
// ---------------------------------------------------------------------------
#define AST 40                       // halves per smem row (conflict-free)
#define TILE_H (128 * AST)
#define GEMM_SMEM_BYTES (STAGES * 2 * TILE_H * 2)

template <int RELU, int OUTH>
__global__ __launch_bounds__(128, 2)
void gemm_h(const __half* __restrict__ A, const __half* __restrict__ Bt,
            const float* __restrict__ bias, float* __restrict__ Cf,
            __half* __restrict__ Ch, int N, int K)
{
    extern __shared__ __half sm[];
    __half* As = sm;                     // [STAGES][128][AST]
    __half* Bs = sm + STAGES * TILE_H;   // [STAGES][128][AST]
    const uint32_t sA = smem_u32(As);
    const uint32_t sB = smem_u32(Bs);

    const int tid  = threadIdx.x;
    const int warp = tid >> 5;
    const int lane = tid & 31;
    const int wm = (warp & 1) * 64;
    const int wn = (warp >> 1) * 64;
    const int g  = lane >> 2;
    const int tg = lane & 3;

    const int bm = blockIdx.y * 128;
    const int bn = blockIdx.x * 128;
    const int ns = K >> 5;

    // ldmatrix per-lane address offsets (halves, within a stage)
    const int a_off = (wm + (lane & 7) + ((lane >> 3) & 1) * 8) * AST
                    + (lane >> 4) * 8;
    const int b_off = (wn + (lane & 7) + (lane >> 4) * 8) * AST
                    + ((lane >> 3) & 1) * 8;

    float acc[4][8][4];
    #pragma unroll
    for (int i = 0; i < 4; i++)
        #pragma unroll
        for (int j = 0; j < 8; j++)
            #pragma unroll
            for (int r = 0; r < 4; r++) acc[i][j][r] = 0.f;

    // per stage: A 128x32 halves = 512 chunks, B same; 128 thr -> 4+4 cp16
    auto load_stage = [&](int s, int buf) {
        const int k0 = s << 5;
        #pragma unroll
        for (int i = 0; i < 4; i++) {
            int f = tid + i * 128;               // 0..511
            int row = f >> 2, ch = f & 3;
            cp16(sA + (buf * TILE_H + row * AST + ch * 8) * 2,
                 A + (size_t)(bm + row) * K + k0 + ch * 8);
        }
        #pragma unroll
        for (int i = 0; i < 4; i++) {
            int f = tid + i * 128;
            int row = f >> 2, ch = f & 3;
            cp16(sB + (buf * TILE_H + row * AST + ch * 8) * 2,
                 Bt + (size_t)(bn + row) * K + k0 + ch * 8);
        }
    };

    #pragma unroll
    for (int s = 0; s < STAGES - 1; s++) {
        load_stage(s, s);
        CP_COMMIT();
    }
    CP_WAIT2();
    __syncthreads();

    for (int s = 0; s < ns; s++) {
        const int buf = s & (STAGES - 1);
        if (s + STAGES - 1 < ns)
            load_stage(s + STAGES - 1, (s + STAGES - 1) & (STAGES - 1));
        CP_COMMIT();

        const uint32_t abB = sA + (buf * TILE_H + a_off) * 2;
        const uint32_t bbB = sB + (buf * TILE_H + b_off) * 2;
        #pragma unroll
        for (int kk = 0; kk < 32; kk += 16) {
            uint32_t a[4][4], b[4][4];
            #pragma unroll
            for (int mi = 0; mi < 4; mi++)
                ldsm4(a[mi][0], a[mi][1], a[mi][2], a[mi][3],
                      abB + (mi * 16 * AST + kk) * 2);
            #pragma unroll
            for (int np = 0; np < 4; np++)
                ldsm4(b[np][0], b[np][1], b[np][2], b[np][3],
                      bbB + (np * 16 * AST + kk) * 2);
            #pragma unroll
            for (int mi = 0; mi < 4; mi++)
                #pragma unroll
                for (int ni = 0; ni < 8; ni++)
                    asm volatile(
                        "mma.sync.aligned.m16n8k16.row.col.f32.f16.f16.f32 "
                        "{%0,%1,%2,%3},{%4,%5,%6,%7},{%8,%9},{%0,%1,%2,%3};"
                        : "+f"(acc[mi][ni][0]), "+f"(acc[mi][ni][1]),
                          "+f"(acc[mi][ni][2]), "+f"(acc[mi][ni][3])
                        : "r"(a[mi][0]), "r"(a[mi][1]),
                          "r"(a[mi][2]), "r"(a[mi][3]),
                          "r"(b[ni >> 1][(ni & 1) * 2]),
                          "r"(b[ni >> 1][(ni & 1) * 2 + 1]));
        }
        CP_WAIT2();
        __syncthreads();
    }

    // epilogue: bias (+ReLU); fp32 or half store
    #pragma unroll
    for (int mi = 0; mi < 4; mi++) {
        int r0 = bm + wm + mi * 16 + g;
        #pragma unroll
        for (int ni = 0; ni < 8; ni++) {
            int c0 = bn + wn + ni * 8 + tg * 2;
            float bv0 = bias[c0], bv1 = bias[c0 + 1];
            float v0 = acc[mi][ni][0] + bv0;
            float v1 = acc[mi][ni][1] + bv1;
            float v2 = acc[mi][ni][2] + bv0;
            float v3 = acc[mi][ni][3] + bv1;
            if (RELU) {
                v0 = fmaxf(v0, 0.f); v1 = fmaxf(v1, 0.f);
                v2 = fmaxf(v2, 0.f); v3 = fmaxf(v3, 0.f);
            }
            if (OUTH) {
                *(half2*)(Ch + (size_t)r0 * N + c0)       = __floats2half2_rn(v0, v1);
                *(half2*)(Ch + (size_t)(r0 + 8) * N + c0) = __floats2half2_rn(v2, v3);
            } else {
                *(float2*)(Cf + (size_t)r0 * N + c0)       = make_float2(v0, v1);
                *(float2*)(Cf + (size_t)(r0 + 8) * N + c0) = make_float2(v2, v3);
            }
        }
    }
}

// ---------------------------------------------------------------------------
__global__ __launch_bounds__(256)
void cvt_half(const float* __restrict__ src, __half* __restrict__ dst)
{
    const size_t i = (size_t)blockIdx.x * blockDim.x + threadIdx.x;
    float4 v = ((const float4*)src)[i];
    ((half2*)dst)[i * 2]     = __floats2half2_rn(v.x, v.y);
    ((half2*)dst)[i * 2 + 1] = __floats2half2_rn(v.z, v.w);
}

// ---------------------------------------------------------------------------
// batched transpose: 11 jobs in one launch; dst[n*K+k] = half(src[k*N+n])
// ---------------------------------------------------------------------------
#define NJOBS 11
struct TJobs {
    const float* src[NJOBS];
    __half*      dst[NJOBS];
    int          K[NJOBS];
    int          N[NJOBS];
};

__global__ __launch_bounds__(256)
void transpose_all(TJobs jobs)
{
    const int j = blockIdx.z;
    const int K = jobs.K[j], N = jobs.N[j];
    const int n0 = blockIdx.x * 32, k0 = blockIdx.y * 32;
    if (n0 >= N || k0 >= K) return;
    const float* src = jobs.src[j];
    __half* dst = jobs.dst[j];

    __shared__ float t[32][33];
    const int tx = threadIdx.x, ty = threadIdx.y;
    #pragma unroll
    for (int i = 0; i < 32; i += 8)
        t[ty + i][tx] = src[(size_t)(k0 + ty + i) * N + n0 + tx];
    __syncthreads();
    #pragma unroll
    for (int i = 0; i < 32; i += 8)
        dst[(size_t)(n0 + ty + i) * K + k0 + tx] = __float2half_rn(t[tx][ty + i]);
}

// ---------------------------------------------------------------------------
// LayerNorm (+residual): x = [x +] LN(z)*g + b (fp32); xr = half(x)
// ---------------------------------------------------------------------------
template <bool RES>
__global__ __launch_bounds__(256)
void ln_kernel(const float* __restrict__ z, float* __restrict__ x,
               __half* __restrict__ xr,
               const float* __restrict__ gamma, const float* __restrict__ beta)
{
    const int row = blockIdx.x;
    const int t   = threadIdx.x;

    float4 v = ((const float4*)(z + (size_t)row * HDIM))[t];
    float s  = v.x + v.y + v.z + v.w;
    float ss = v.x * v.x + v.y * v.y + v.z * v.z + v.w * v.w;
    #pragma unroll
    for (int o = 16; o; o >>= 1) {
        s  += __shfl_xor_sync(0xffffffffu, s, o);
        ss += __shfl_xor_sync(0xffffffffu, ss, o);
    }
    __shared__ float sbuf[16];
    const int w = t >> 5, l = t & 31;
    if (l == 0) { sbuf[w] = s; sbuf[8 + w] = ss; }
    __syncthreads();
    float tot = 0.f, tot2 = 0.f;
    #pragma unroll
    for (int i = 0; i < 8; i++) { tot += sbuf[i]; tot2 += sbuf[8 + i]; }

    const float inv  = 1.f / (float)HDIM;
    const float mu   = tot * inv;
    const float var  = tot2 * inv - mu * mu;
    const float rstd = rsqrtf(var + 1e-5f);

    float4 gm = ((const float4*)gamma)[t];
    float4 bt = ((const float4*)beta)[t];
    float4 o;
    o.x = (v.x - mu) * rstd * gm.x + bt.x;
    o.y = (v.y - mu) * rstd * gm.y + bt.y;
    o.z = (v.z - mu) * rstd * gm.z + bt.z;
    o.w = (v.w - mu) * rstd * gm.w + bt.w;
    if (RES) {
        float4 xv = ((const float4*)(x + (size_t)row * HDIM))[t];
        o.x += xv.x; o.y += xv.y; o.z += xv.z; o.w += xv.w;
    }
    ((float4*)(x + (size_t)row * HDIM))[t] = o;
    ((half2*)(xr + (size_t)row * HDIM))[t * 2]     = __floats2half2_rn(o.x, o.y);
    ((half2*)(xr + (size_t)row * HDIM))[t * 2 + 1] = __floats2half2_rn(o.z, o.w);
}

// ---------------------------------------------------------------------------
// logits[b,a] = dot(xe[b], emb[b,a]); 8 actions per warp pass (16 streams)
// ---------------------------------------------------------------------------
__global__ __launch_bounds__(256)
void logits_kernel(const float* __restrict__ xe, const float* __restrict__ emb,
                   const int* __restrict__ idx, float* __restrict__ out)
{
    const int b = blockIdx.x;
    __shared__ float4 xs[EDIM / 4];
    const int t = threadIdx.x;
    if (t < EDIM / 4) xs[t] = ((const float4*)(xe + (size_t)b * EDIM))[t];
    __syncthreads();

    const int warp = t >> 5, lane = t & 31;
    const float4* ebase = (const float4*)(emb + (size_t)b * ADIM * EDIM);

    #pragma unroll
    for (int a0 = warp * 8; a0 < ADIM; a0 += 64) {
        float acc[8] = {0.f, 0.f, 0.f, 0.f, 0.f, 0.f, 0.f, 0.f};
        #pragma unroll
        for (int i = 0; i < 2; i++) {
            float4 xv = xs[lane + 32 * i];
            #pragma unroll
            for (int j = 0; j < 8; j++) {
                float4 v = ebase[(size_t)(a0 + j) * (EDIM / 4) + lane + 32 * i];
                acc[j] += v.x * xv.x + v.y * xv.y + v.z * xv.z + v.w * xv.w;
            }
        }
        #pragma unroll
        for (int o = 16; o; o >>= 1)
            #pragma unroll
            for (int j = 0; j < 8; j++)
                acc[j] += __shfl_xor_sync(0xffffffffu, acc[j], o);
        if (lane < 8) {
            int a = a0 + lane;
            int4 ii = ((const int4*)idx)[(size_t)b * ADIM + a];
            bool mask = (ii.x + ii.y + ii.z + ii.w) == 0;
            out[(size_t)b * ADIM + a] = mask ? __int_as_float(0xff800000)
                                             : acc[lane];
        }
    }
}

// ---------------------------------------------------------------------------
extern "C" void kernel_launch(void* const* d_in, const int* in_sizes, int n_in,
                              void* d_out, int out_size)
{
    (void)in_sizes; (void)n_in; (void)out_size;
    const float* obs   = (const float*)d_in[0];
    const float* emb   = (const float*)d_in[1];
    const int*   idx   = (const int*)d_in[2];
    const float* w0    = (const float*)d_in[3];
    const float* b0    = (const float*)d_in[4];
    const float* g0    = (const float*)d_in[5];
    const float* be0   = (const float*)d_in[6];
    const float* Wb    = (const float*)d_in[7];
    const float* bb    = (const float*)d_in[8];
    const float* gb    = (const float*)d_in[9];
    const float* betab = (const float*)d_in[10];
    const float* w1    = (const float*)d_in[11];
    const float* b1    = (const float*)d_in[12];
    const float* w2    = (const float*)d_in[13];
    const float* b2    = (const float*)d_in[14];
    float* out = (float*)d_out;

    float  *x, *z, *e;
    __half *xr, *zh, *a0, *wt;
    cudaGetSymbolAddress((void**)&x,  g_x);
    cudaGetSymbolAddress((void**)&xr, g_xr);
    cudaGetSymbolAddress((void**)&z,  g_z);
    cudaGetSymbolAddress((void**)&zh, g_zh);
    cudaGetSymbolAddress((void**)&e,  g_e);
    cudaGetSymbolAddress((void**)&a0, g_a0);
    cudaGetSymbolAddress((void**)&wt, g_wt);
    __half* wt0 = wt + WT0_OFF;
    __half* wtb = wt + WTB_OFF;
    __half* wt1 = wt + WT1_OFF;
    __half* wt2 = wt + WT2_OFF;

    cudaFuncSetAttribute(gemm_h<1, 0>, cudaFuncAttributeMaxDynamicSharedMemorySize,
                         GEMM_SMEM_BYTES);
    cudaFuncSetAttribute(gemm_h<1, 1>, cudaFuncAttributeMaxDynamicSharedMemorySize,
                         GEMM_SMEM_BYTES);
    cudaFuncSetAttribute(gemm_h<0, 0>, cudaFuncAttributeMaxDynamicSharedMemorySize,
                         GEMM_SMEM_BYTES);

    const dim3 blk(256);
    const dim3 tblk(32, 8);

    // preprocess: obs -> half; all weights -> transposed half in ONE launch
    cvt_half<<<(BATCH * EDIM) / 1024, blk>>>(obs, a0);
    {
        TJobs jobs;
        jobs.src[0] = w0;  jobs.dst[0] = wt0; jobs.K[0] = EDIM; jobs.N[0] = HDIM;
        for (int i = 0; i < NLAYER; i++) {
            jobs.src[1 + i] = Wb + (size_t)i * HDIM * HDIM;
            jobs.dst[1 + i] = wtb + (size_t)i * HDIM * HDIM;
            jobs.K[1 + i] = HDIM; jobs.N[1 + i] = HDIM;
        }
        jobs.src[9]  = w1; jobs.dst[9]  = wt1; jobs.K[9]  = HDIM; jobs.N[9]  = HDIM;
        jobs.src[10] = w2; jobs.dst[10] = wt2; jobs.K[10] = HDIM; jobs.N[10] = EDIM;
        transpose_all<<<dim3(32, 32, NJOBS), tblk>>>(jobs);
    }

    const dim3 gblk(128);
    const dim3 gridH(HDIM / 128, BATCH / 128);   // (8, 128)
    const dim3 gridE(EDIM / 128, BATCH / 128);   // (2, 128)

    gemm_h<1, 0><<<gridH, gblk, GEMM_SMEM_BYTES>>>(a0, wt0, b0, z, nullptr,
                                                   HDIM, EDIM);
    ln_kernel<false><<<BATCH, blk>>>(z, x, xr, g0, be0);

    for (int i = 0; i < NLAYER; i++) {
        gemm_h<1, 0><<<gridH, gblk, GEMM_SMEM_BYTES>>>(
            xr, wtb + (size_t)i * HDIM * HDIM, bb + (size_t)i * HDIM, z, nullptr,
            HDIM, HDIM);
        ln_kernel<true><<<BATCH, blk>>>(z, x, xr, gb + (size_t)i * HDIM,
                                        betab + (size_t)i * HDIM);
    }

    gemm_h<1, 1><<<gridH, gblk, GEMM_SMEM_BYTES>>>(xr, wt1, b1, nullptr, zh,
                                                   HDIM, HDIM);
    gemm_h<0, 0><<<gridE, gblk, GEMM_SMEM_BYTES>>>(zh, wt2, b2, e, nullptr,
                                                   EDIM, HDIM);

    logits_kernel<<<BATCH, blk>>>(e, emb, idx, out);
}